// round 11
// baseline (speedup 1.0000x reference)
#include <cuda_runtime.h>
#include <math.h>

#define G      1024
#define GI     (G - 2)
#define B      4
#define N_TOT  (B * G * G)

__device__ float g_w  [N_TOT];   // exp(mu * prev_pre)
__device__ float g_h  [N_TOT];   // 0.5 / y3   (0 on boundary)
__device__ float g_F  [N_TOT];   // f*H^2 / y3 (0 on boundary)
__device__ float g_u0 [N_TOT];
__device__ float g_u1 [N_TOT];

__device__ __forceinline__ float4 ldcs4(const float* p) {
    return __ldcs((const float4*)p);
}

// ---------- fused precompute + init: w, h, F, u0 (u1 border) in one pass ----------
__global__ void __launch_bounds__(256)
k_pre(const float* __restrict__ prev, const float* __restrict__ f,
      const float* __restrict__ mu, const float* __restrict__ pre) {
    // let the first sweep's CTAs launch early (they wait before touching w/h/F)
    asm volatile("griddepcontrol.launch_dependents;" ::: "memory");

    int j0 = (blockIdx.x * blockDim.x + threadIdx.x) * 4;   // 0..1020
    int i  = blockIdx.y * blockDim.y + threadIdx.y;         // 0..1023
    int b  = blockIdx.z;
    int base = (b * G + i) * G + j0;
    float m = mu[0];

    float4 pC = ldcs4(prev + base);
    float4 pN = (i > 0)     ? ldcs4(prev + base - G) : make_float4(0, 0, 0, 0);
    float4 pS = (i < G - 1) ? ldcs4(prev + base + G) : make_float4(0, 0, 0, 0);
    float  pL = (j0 > 0)     ? __ldcs(prev + base - 1) : 0.0f;
    float  pR = (j0 < G - 4) ? __ldcs(prev + base + 4) : 0.0f;

    float wc[6] = { expf(m * pL), expf(m * pC.x), expf(m * pC.y),
                    expf(m * pC.z), expf(m * pC.w), expf(m * pR) };
    float wn[4] = { expf(m * pN.x), expf(m * pN.y), expf(m * pN.z), expf(m * pN.w) };
    float ws[4] = { expf(m * pS.x), expf(m * pS.y), expf(m * pS.z), expf(m * pS.w) };

    *(float4*)(g_w + base) = make_float4(wc[1], wc[2], wc[3], wc[4]);

    float4 fC = ldcs4(f + base);
    float ff[4] = { fC.x, fC.y, fC.z, fC.w };

    bool rowIn = (i >= 1 && i <= G - 2);
    const float HH = (1.0f / 1023.0f) * (1.0f / 1023.0f);
    float h[4], Fo[4], u0v[4];
#pragma unroll
    for (int k = 0; k < 4; ++k) {
        int j = j0 + k;
        bool in = rowIn && (j >= 1 && j <= G - 2);
        float y3  = 0.5f * (wn[k] + ws[k] + wc[k] + wc[k + 2]) + 2.0f * wc[k + 1];
        float iy3 = 1.0f / y3;
        h[k]  = in ? 0.5f * iy3       : 0.0f;
        Fo[k] = in ? ff[k] * HH * iy3 : 0.0f;
        u0v[k] = in ? __ldcs(pre + ((long)b * GI + (i - 1)) * GI + (j - 1)) : 0.0f;
    }
    *(float4*)(g_h  + base) = make_float4(h[0], h[1], h[2], h[3]);
    *(float4*)(g_F  + base) = make_float4(Fo[0], Fo[1], Fo[2], Fo[3]);
    *(float4*)(g_u0 + base) = make_float4(u0v[0], u0v[1], u0v[2], u0v[3]);

    if (i == 0 || i == G - 1) {
        *(float4*)(g_u1 + base) = make_float4(0, 0, 0, 0);
    } else if (j0 == 0) {
        g_u1[base] = 0.0f;
    } else if (j0 == G - 4) {
        g_u1[base + 3] = 0.0f;
    }
}

// ---------- one Jacobi sweep with PDL ----------
// launch_dependents at the very top: dependents' launch is gated only by all our
// CTAs reaching that point; their correctness is enforced by their own wait.
// PREWAIT=true (sweep 1): wait BEFORE phase A, since the producer (k_pre) writes
// the invariant arrays. PREWAIT=false (sweeps 2+): invariant loads pre-wait.
template <bool FINAL, bool PREWAIT>
__global__ void __launch_bounds__(256)
k_step(const float* __restrict__ u, float* __restrict__ dst) {
    asm volatile("griddepcontrol.launch_dependents;" ::: "memory");

    int j0 = (blockIdx.x * blockDim.x + threadIdx.x) * 4;   // 0..1020
    int i  = blockIdx.y * blockDim.y + threadIdx.y + 1;     // 1..1024
    int b  = blockIdx.z;
    if (i > G - 2) {
        asm volatile("griddepcontrol.wait;" ::: "memory");
        return;
    }
    int idx = (b * G + i) * G + j0;

    if (PREWAIT) asm volatile("griddepcontrol.wait;" ::: "memory");

    // --- phase A: iteration-invariant operands ---
    float4 wC4 = *(const float4*)(g_w + idx);
    float4 wN4 = *(const float4*)(g_w + idx - G);
    float4 wS4 = *(const float4*)(g_w + idx + G);
    float  wLl = g_w[idx - 1];
    float  wRr = g_w[idx + 4];
    float4 h4 = *(const float4*)(g_h + idx);
    float4 F4 = *(const float4*)(g_F + idx);

    if (!PREWAIT) asm volatile("griddepcontrol.wait;" ::: "memory");

    // --- phase B: dependent u loads ---
    float4 uC4 = *(const float4*)(u + idx);
    float4 uN4 = *(const float4*)(u + idx - G);
    float4 uS4 = *(const float4*)(u + idx + G);
    float  uLl = u[idx - 1];
    float  uRr = u[idx + 4];

    float uc[6] = { uLl, uC4.x, uC4.y, uC4.z, uC4.w, uRr };
    float wc[6] = { wLl, wC4.x, wC4.y, wC4.z, wC4.w, wRr };
    float un[4] = { uN4.x, uN4.y, uN4.z, uN4.w };
    float us[4] = { uS4.x, uS4.y, uS4.z, uS4.w };
    float wn[4] = { wN4.x, wN4.y, wN4.z, wN4.w };
    float ws[4] = { wS4.x, wS4.y, wS4.z, wS4.w };
    float hh[4] = { h4.x, h4.y, h4.z, h4.w };
    float ff[4] = { F4.x, F4.y, F4.z, F4.w };

    float r[4];
#pragma unroll
    for (int k = 0; k < 4; ++k) {
        float uW = uc[k], uE = uc[k + 2];
        float s = wc[k + 1] * (uW + uE + un[k] + us[k]);
        s = fmaf(wc[k],     uW,    s);
        s = fmaf(wc[k + 2], uE,    s);
        s = fmaf(wn[k],     un[k], s);
        s = fmaf(ws[k],     us[k], s);
        r[k] = fmaf(hh[k], s, ff[k]);   // boundary cells: h=F=0 -> exactly 0
    }

    if (FINAL) {
        long obase = ((long)b * GI + (i - 1)) * GI;
#pragma unroll
        for (int k = 0; k < 4; ++k) {
            int j = j0 + k;
            if (j >= 1 && j <= G - 2)
                __stcs(dst + obase + (j - 1), r[k]);
        }
    } else {
        *(float4*)(dst + idx) = make_float4(r[0], r[1], r[2], r[3]);
    }
}

extern "C" void kernel_launch(void* const* d_in, const int* in_sizes, int n_in,
                              void* d_out, int out_size) {
    const float* pre  = (const float*)d_in[0];   // [B,1,1022,1022]
    const float* f    = (const float*)d_in[1];   // [B,1,1024,1024]
    const float* mu   = (const float*)d_in[2];   // [1]
    const float* prev = (const float*)d_in[3];   // [B,1,1024,1024]
    // d_in[4] = maxiter (fixed = 20 -> 21 total steps)
    float* out = (float*)d_out;

    float *u0p, *u1p;
    cudaGetSymbolAddress((void**)&u0p, g_u0);
    cudaGetSymbolAddress((void**)&u1p, g_u1);

    // PDL launch config (shared)
    cudaLaunchAttribute at;
    at.id = cudaLaunchAttributeProgrammaticStreamSerialization;
    at.val.programmaticStreamSerializationAllowed = 1;

    // fused precompute + init (normal launch; first in stream)
    dim3 pblk(32, 8, 1);
    dim3 pgrd(G / 128, G / 8, B);
    k_pre<<<pgrd, pblk>>>(prev, f, mu, pre);

    dim3 sblk(32, 8, 1);
    dim3 sgrd(G / 128, (GI + 7) / 8, B);  // 4096 blocks

    cudaLaunchConfig_t cfg = {};
    cfg.gridDim = sgrd;
    cfg.blockDim = sblk;
    cfg.dynamicSmemBytes = 0;
    cfg.stream = 0;
    cfg.attrs = &at;
    cfg.numAttrs = 1;

    // sweep 1: PDL with wait-before-everything (k_pre writes the invariants)
    cudaLaunchKernelEx(&cfg, k_step<false, true>, (const float*)u0p, u1p);

    // sweeps 2..21: PDL with invariant prefetch before wait
    for (int t = 1; t < 20; ++t) {
        const float* src = (t & 1) ? u1p : u0p;
        float*       dst = (t & 1) ? u0p : u1p;
        cudaLaunchKernelEx(&cfg, k_step<false, false>, src, dst);
    }
    cudaLaunchKernelEx(&cfg, k_step<true, false>, (const float*)u0p, out);  // t=20: src u0
}

// round 12
// speedup vs baseline: 1.0366x; 1.0366x over previous
#include <cuda_runtime.h>
#include <math.h>

#define G      1024
#define GI     (G - 2)
#define B      4
#define N_TOT  (B * G * G)

__device__ float g_w  [N_TOT];   // exp(mu * prev_pre)
__device__ float g_h  [N_TOT];   // 0.5 / y3   (0 on boundary)
__device__ float g_F  [N_TOT];   // f*H^2 / y3 (0 on boundary)
__device__ float g_u0 [N_TOT];
__device__ float g_u1 [N_TOT];

__device__ __forceinline__ float4 ldcs4(const float* p) {
    return __ldcs((const float4*)p);
}

// ---------- fused precompute + init: w, h, F, u0 (u1 border) in one pass ----------
__global__ void __launch_bounds__(256)
k_pre(const float* __restrict__ prev, const float* __restrict__ f,
      const float* __restrict__ mu, const float* __restrict__ pre) {
    int j0 = (blockIdx.x * blockDim.x + threadIdx.x) * 4;   // 0..1020
    int i  = blockIdx.y * blockDim.y + threadIdx.y;         // 0..1023
    int b  = blockIdx.z;
    int base = (b * G + i) * G + j0;
    float m = mu[0];

    float4 pC = ldcs4(prev + base);
    float4 pN = (i > 0)     ? ldcs4(prev + base - G) : make_float4(0, 0, 0, 0);
    float4 pS = (i < G - 1) ? ldcs4(prev + base + G) : make_float4(0, 0, 0, 0);
    float  pL = (j0 > 0)     ? __ldcs(prev + base - 1) : 0.0f;
    float  pR = (j0 < G - 4) ? __ldcs(prev + base + 4) : 0.0f;

    float wc[6] = { expf(m * pL), expf(m * pC.x), expf(m * pC.y),
                    expf(m * pC.z), expf(m * pC.w), expf(m * pR) };
    float wn[4] = { expf(m * pN.x), expf(m * pN.y), expf(m * pN.z), expf(m * pN.w) };
    float ws[4] = { expf(m * pS.x), expf(m * pS.y), expf(m * pS.z), expf(m * pS.w) };

    *(float4*)(g_w + base) = make_float4(wc[1], wc[2], wc[3], wc[4]);

    float4 fC = ldcs4(f + base);
    float ff[4] = { fC.x, fC.y, fC.z, fC.w };

    bool rowIn = (i >= 1 && i <= G - 2);
    const float HH = (1.0f / 1023.0f) * (1.0f / 1023.0f);
    float h[4], Fo[4], u0v[4];
#pragma unroll
    for (int k = 0; k < 4; ++k) {
        int j = j0 + k;
        bool in = rowIn && (j >= 1 && j <= G - 2);
        float y3  = 0.5f * (wn[k] + ws[k] + wc[k] + wc[k + 2]) + 2.0f * wc[k + 1];
        float iy3 = 1.0f / y3;
        h[k]  = in ? 0.5f * iy3       : 0.0f;
        Fo[k] = in ? ff[k] * HH * iy3 : 0.0f;
        u0v[k] = in ? __ldcs(pre + ((long)b * GI + (i - 1)) * GI + (j - 1)) : 0.0f;
    }
    *(float4*)(g_h  + base) = make_float4(h[0], h[1], h[2], h[3]);
    *(float4*)(g_F  + base) = make_float4(Fo[0], Fo[1], Fo[2], Fo[3]);
    *(float4*)(g_u0 + base) = make_float4(u0v[0], u0v[1], u0v[2], u0v[3]);

    if (i == 0 || i == G - 1) {
        *(float4*)(g_u1 + base) = make_float4(0, 0, 0, 0);
    } else if (j0 == 0) {
        g_u1[base] = 0.0f;
    } else if (j0 == G - 4) {
        g_u1[base + 3] = 0.0f;
    }

    // release sweep 1 (it waits before touching anything we wrote)
    asm volatile("griddepcontrol.launch_dependents;" ::: "memory");
}

// ---------- one Jacobi sweep with PDL (R10 placement) ----------
// PREWAIT=true (sweep 1): producer wrote the invariants -> wait before ALL loads.
// PREWAIT=false (sweeps 2+): invariant w/h/F loads issue pre-wait; wait; u loads;
// then launch_dependents -> next sweep's invariant phase overlaps our tail.
template <bool FINAL, bool PREWAIT>
__global__ void __launch_bounds__(256)
k_step(const float* __restrict__ u, float* __restrict__ dst) {
    int j0 = (blockIdx.x * blockDim.x + threadIdx.x) * 4;   // 0..1020
    int i  = blockIdx.y * blockDim.y + threadIdx.y + 1;     // 1..1024
    int b  = blockIdx.z;
    if (i > G - 2) {
        asm volatile("griddepcontrol.wait;" ::: "memory");
        asm volatile("griddepcontrol.launch_dependents;" ::: "memory");
        return;
    }
    int idx = (b * G + i) * G + j0;

    if (PREWAIT) asm volatile("griddepcontrol.wait;" ::: "memory");

    // --- phase A: iteration-invariant operands ---
    float4 wC4 = *(const float4*)(g_w + idx);
    float4 wN4 = *(const float4*)(g_w + idx - G);
    float4 wS4 = *(const float4*)(g_w + idx + G);
    float  wLl = g_w[idx - 1];
    float  wRr = g_w[idx + 4];
    float4 h4 = *(const float4*)(g_h + idx);
    float4 F4 = *(const float4*)(g_F + idx);

    if (!PREWAIT) asm volatile("griddepcontrol.wait;" ::: "memory");

    // --- phase B: dependent u loads ---
    float4 uC4 = *(const float4*)(u + idx);
    float4 uN4 = *(const float4*)(u + idx - G);
    float4 uS4 = *(const float4*)(u + idx + G);
    float  uLl = u[idx - 1];
    float  uRr = u[idx + 4];

    asm volatile("griddepcontrol.launch_dependents;" ::: "memory");

    float uc[6] = { uLl, uC4.x, uC4.y, uC4.z, uC4.w, uRr };
    float wc[6] = { wLl, wC4.x, wC4.y, wC4.z, wC4.w, wRr };
    float un[4] = { uN4.x, uN4.y, uN4.z, uN4.w };
    float us[4] = { uS4.x, uS4.y, uS4.z, uS4.w };
    float wn[4] = { wN4.x, wN4.y, wN4.z, wN4.w };
    float ws[4] = { wS4.x, wS4.y, wS4.z, wS4.w };
    float hh[4] = { h4.x, h4.y, h4.z, h4.w };
    float ff[4] = { F4.x, F4.y, F4.z, F4.w };

    float r[4];
#pragma unroll
    for (int k = 0; k < 4; ++k) {
        float uW = uc[k], uE = uc[k + 2];
        float s = wc[k + 1] * (uW + uE + un[k] + us[k]);
        s = fmaf(wc[k],     uW,    s);
        s = fmaf(wc[k + 2], uE,    s);
        s = fmaf(wn[k],     un[k], s);
        s = fmaf(ws[k],     us[k], s);
        r[k] = fmaf(hh[k], s, ff[k]);   // boundary cells: h=F=0 -> exactly 0
    }

    if (FINAL) {
        long obase = ((long)b * GI + (i - 1)) * GI;
#pragma unroll
        for (int k = 0; k < 4; ++k) {
            int j = j0 + k;
            if (j >= 1 && j <= G - 2)
                __stcs(dst + obase + (j - 1), r[k]);
        }
    } else {
        *(float4*)(dst + idx) = make_float4(r[0], r[1], r[2], r[3]);
    }
}

extern "C" void kernel_launch(void* const* d_in, const int* in_sizes, int n_in,
                              void* d_out, int out_size) {
    const float* pre  = (const float*)d_in[0];   // [B,1,1022,1022]
    const float* f    = (const float*)d_in[1];   // [B,1,1024,1024]
    const float* mu   = (const float*)d_in[2];   // [1]
    const float* prev = (const float*)d_in[3];   // [B,1,1024,1024]
    // d_in[4] = maxiter (fixed = 20 -> 21 total steps)
    float* out = (float*)d_out;

    float *u0p, *u1p;
    cudaGetSymbolAddress((void**)&u0p, g_u0);
    cudaGetSymbolAddress((void**)&u1p, g_u1);

    // fused precompute + init (plain launch, first in stream)
    dim3 pblk(32, 8, 1);
    dim3 pgrd(G / 128, G / 8, B);
    k_pre<<<pgrd, pblk>>>(prev, f, mu, pre);

    dim3 sblk(32, 8, 1);
    dim3 sgrd(G / 128, (GI + 7) / 8, B);  // 4096 blocks

    cudaLaunchAttribute at;
    at.id = cudaLaunchAttributeProgrammaticStreamSerialization;
    at.val.programmaticStreamSerializationAllowed = 1;

    cudaLaunchConfig_t cfg = {};
    cfg.gridDim = sgrd;
    cfg.blockDim = sblk;
    cfg.dynamicSmemBytes = 0;
    cfg.stream = 0;
    cfg.attrs = &at;
    cfg.numAttrs = 1;

    // sweep 1: PDL, wait before everything (k_pre wrote the invariants)
    cudaLaunchKernelEx(&cfg, k_step<false, true>, (const float*)u0p, u1p);

    // sweeps 2..21: PDL, invariant prefetch pre-wait (R10 placement)
    for (int t = 1; t < 20; ++t) {
        const float* src = (t & 1) ? u1p : u0p;
        float*       dst = (t & 1) ? u0p : u1p;
        cudaLaunchKernelEx(&cfg, k_step<false, false>, src, dst);
    }
    cudaLaunchKernelEx(&cfg, k_step<true, false>, (const float*)u0p, out);  // t=20: src u0
}

// round 13
// speedup vs baseline: 1.0477x; 1.0108x over previous
#include <cuda_runtime.h>
#include <math.h>

#define G      1024
#define GI     (G - 2)
#define B      4
#define N_TOT  (B * G * G)

__device__ float g_w  [N_TOT];   // exp(mu * prev_pre)
__device__ float g_h  [N_TOT];   // 0.5 / y3   (0 on boundary)
__device__ float g_F  [N_TOT];   // f*H^2 / y3 (0 on boundary)
__device__ float g_u0 [N_TOT];
__device__ float g_u1 [N_TOT];

__device__ __forceinline__ float4 ldcs4(const float* p) {
    return __ldcs((const float4*)p);
}

// padded read of the unpadded [GI x GI] initial field (zero boundary)
__device__ __forceinline__ float ppre(const float* __restrict__ pre, int b, int i, int j) {
    if (i >= 1 && i <= G - 2 && j >= 1 && j <= G - 2)
        return __ldcs(pre + ((long)b * GI + (i - 1)) * GI + (j - 1));
    return 0.0f;
}

// ---------- fused precompute + STEP 1: w, h, F, u1 = step(pad(pre)) in one pass ----------
__global__ void __launch_bounds__(256)
k_pre(const float* __restrict__ prev, const float* __restrict__ f,
      const float* __restrict__ mu, const float* __restrict__ pre) {
    int j0 = (blockIdx.x * blockDim.x + threadIdx.x) * 4;   // 0..1020
    int i  = blockIdx.y * blockDim.y + threadIdx.y;         // 0..1023
    int b  = blockIdx.z;
    int base = (b * G + i) * G + j0;
    float m = mu[0];

    float4 pC = ldcs4(prev + base);
    float4 pN = (i > 0)     ? ldcs4(prev + base - G) : make_float4(0, 0, 0, 0);
    float4 pS = (i < G - 1) ? ldcs4(prev + base + G) : make_float4(0, 0, 0, 0);
    float  pL = (j0 > 0)     ? __ldcs(prev + base - 1) : 0.0f;
    float  pR = (j0 < G - 4) ? __ldcs(prev + base + 4) : 0.0f;

    float wc[6] = { expf(m * pL), expf(m * pC.x), expf(m * pC.y),
                    expf(m * pC.z), expf(m * pC.w), expf(m * pR) };
    float wn[4] = { expf(m * pN.x), expf(m * pN.y), expf(m * pN.z), expf(m * pN.w) };
    float ws[4] = { expf(m * pS.x), expf(m * pS.y), expf(m * pS.z), expf(m * pS.w) };

    *(float4*)(g_w + base) = make_float4(wc[1], wc[2], wc[3], wc[4]);

    float4 fC = ldcs4(f + base);
    float ff[4] = { fC.x, fC.y, fC.z, fC.w };

    bool rowIn = (i >= 1 && i <= G - 2);
    const float HH = (1.0f / 1023.0f) * (1.0f / 1023.0f);
    float h[4], Fo[4];
#pragma unroll
    for (int k = 0; k < 4; ++k) {
        int j = j0 + k;
        bool in = rowIn && (j >= 1 && j <= G - 2);
        float y3  = 0.5f * (wn[k] + ws[k] + wc[k] + wc[k + 2]) + 2.0f * wc[k + 1];
        float iy3 = 1.0f / y3;
        h[k]  = in ? 0.5f * iy3       : 0.0f;
        Fo[k] = in ? ff[k] * HH * iy3 : 0.0f;
    }
    *(float4*)(g_h + base) = make_float4(h[0], h[1], h[2], h[3]);
    *(float4*)(g_F + base) = make_float4(Fo[0], Fo[1], Fo[2], Fo[3]);

    // ---- step 1 inline: u1 = h*(wC*sum(u0_n) + sum(w_n*u0_n)) + F, u0 = pad(pre) ----
    float uc0[6], un0[4], us0[4];
#pragma unroll
    for (int k = 0; k < 6; ++k) uc0[k] = ppre(pre, b, i, j0 - 1 + k);
#pragma unroll
    for (int k = 0; k < 4; ++k) {
        un0[k] = ppre(pre, b, i - 1, j0 + k);
        us0[k] = ppre(pre, b, i + 1, j0 + k);
    }
    float u1v[4];
#pragma unroll
    for (int k = 0; k < 4; ++k) {
        float uW = uc0[k], uE = uc0[k + 2], uN = un0[k], uS = us0[k];
        float s = wc[k + 1] * (uW + uE + uN + uS);
        s = fmaf(wc[k],     uW, s);
        s = fmaf(wc[k + 2], uE, s);
        s = fmaf(wn[k],     uN, s);
        s = fmaf(ws[k],     uS, s);
        u1v[k] = fmaf(h[k], s, Fo[k]);    // boundary cells: h=F=0 -> exactly 0
    }
    *(float4*)(g_u1 + base) = make_float4(u1v[0], u1v[1], u1v[2], u1v[3]);

    // u0: only border ROWS need zeroing (border cols are written as exact zeros
    // by every sweep's full-row float4 stores; interior is overwritten by sweep k=0)
    if (i == 0 || i == G - 1) {
        *(float4*)(g_u0 + base) = make_float4(0, 0, 0, 0);
    }

    // release the first sweep (it waits before touching anything we wrote)
    asm volatile("griddepcontrol.launch_dependents;" ::: "memory");
}

// ---------- one Jacobi sweep with PDL (R10 placement) ----------
template <bool FINAL, bool PREWAIT>
__global__ void __launch_bounds__(256)
k_step(const float* __restrict__ u, float* __restrict__ dst) {
    int j0 = (blockIdx.x * blockDim.x + threadIdx.x) * 4;   // 0..1020
    int i  = blockIdx.y * blockDim.y + threadIdx.y + 1;     // 1..1024
    int b  = blockIdx.z;
    if (i > G - 2) {
        asm volatile("griddepcontrol.wait;" ::: "memory");
        asm volatile("griddepcontrol.launch_dependents;" ::: "memory");
        return;
    }
    int idx = (b * G + i) * G + j0;

    if (PREWAIT) asm volatile("griddepcontrol.wait;" ::: "memory");

    // --- phase A: iteration-invariant operands ---
    float4 wC4 = *(const float4*)(g_w + idx);
    float4 wN4 = *(const float4*)(g_w + idx - G);
    float4 wS4 = *(const float4*)(g_w + idx + G);
    float  wLl = g_w[idx - 1];
    float  wRr = g_w[idx + 4];
    float4 h4 = *(const float4*)(g_h + idx);
    float4 F4 = *(const float4*)(g_F + idx);

    if (!PREWAIT) asm volatile("griddepcontrol.wait;" ::: "memory");

    // --- phase B: dependent u loads ---
    float4 uC4 = *(const float4*)(u + idx);
    float4 uN4 = *(const float4*)(u + idx - G);
    float4 uS4 = *(const float4*)(u + idx + G);
    float  uLl = u[idx - 1];
    float  uRr = u[idx + 4];

    asm volatile("griddepcontrol.launch_dependents;" ::: "memory");

    float uc[6] = { uLl, uC4.x, uC4.y, uC4.z, uC4.w, uRr };
    float wc[6] = { wLl, wC4.x, wC4.y, wC4.z, wC4.w, wRr };
    float un[4] = { uN4.x, uN4.y, uN4.z, uN4.w };
    float us[4] = { uS4.x, uS4.y, uS4.z, uS4.w };
    float wn[4] = { wN4.x, wN4.y, wN4.z, wN4.w };
    float ws[4] = { wS4.x, wS4.y, wS4.z, wS4.w };
    float hh[4] = { h4.x, h4.y, h4.z, h4.w };
    float ff[4] = { F4.x, F4.y, F4.z, F4.w };

    float r[4];
#pragma unroll
    for (int k = 0; k < 4; ++k) {
        float uW = uc[k], uE = uc[k + 2];
        float s = wc[k + 1] * (uW + uE + un[k] + us[k]);
        s = fmaf(wc[k],     uW,    s);
        s = fmaf(wc[k + 2], uE,    s);
        s = fmaf(wn[k],     un[k], s);
        s = fmaf(ws[k],     us[k], s);
        r[k] = fmaf(hh[k], s, ff[k]);   // boundary cells: h=F=0 -> exactly 0
    }

    if (FINAL) {
        long obase = ((long)b * GI + (i - 1)) * GI;
#pragma unroll
        for (int k = 0; k < 4; ++k) {
            int j = j0 + k;
            if (j >= 1 && j <= G - 2)
                __stcs(dst + obase + (j - 1), r[k]);
        }
    } else {
        *(float4*)(dst + idx) = make_float4(r[0], r[1], r[2], r[3]);
    }
}

extern "C" void kernel_launch(void* const* d_in, const int* in_sizes, int n_in,
                              void* d_out, int out_size) {
    const float* pre  = (const float*)d_in[0];   // [B,1,1022,1022]
    const float* f    = (const float*)d_in[1];   // [B,1,1024,1024]
    const float* mu   = (const float*)d_in[2];   // [1]
    const float* prev = (const float*)d_in[3];   // [B,1,1024,1024]
    // d_in[4] = maxiter (fixed = 20 -> 21 total steps; step 1 fused into k_pre)
    float* out = (float*)d_out;

    float *u0p, *u1p;
    cudaGetSymbolAddress((void**)&u0p, g_u0);
    cudaGetSymbolAddress((void**)&u1p, g_u1);

    // fused precompute + step 1 (plain launch, first in stream)
    dim3 pblk(32, 8, 1);
    dim3 pgrd(G / 128, G / 8, B);
    k_pre<<<pgrd, pblk>>>(prev, f, mu, pre);

    dim3 sblk(32, 8, 1);
    dim3 sgrd(G / 128, (GI + 7) / 8, B);  // 4096 blocks

    cudaLaunchAttribute at;
    at.id = cudaLaunchAttributeProgrammaticStreamSerialization;
    at.val.programmaticStreamSerializationAllowed = 1;

    cudaLaunchConfig_t cfg = {};
    cfg.gridDim = sgrd;
    cfg.blockDim = sblk;
    cfg.dynamicSmemBytes = 0;
    cfg.stream = 0;
    cfg.attrs = &at;
    cfg.numAttrs = 1;

    // steps 2..21 = 20 sweep launches; even k: u1->u0, odd k: u0->u1
    // k=0: PREWAIT (k_pre wrote invariants AND u1). k=19 (odd, src u0): FINAL -> out
    cudaLaunchKernelEx(&cfg, k_step<false, true>, (const float*)u1p, u0p);
    for (int k = 1; k < 19; ++k) {
        const float* src = (k & 1) ? u0p : u1p;
        float*       dst = (k & 1) ? u1p : u0p;
        cudaLaunchKernelEx(&cfg, k_step<false, false>, src, dst);
    }
    cudaLaunchKernelEx(&cfg, k_step<true, false>, (const float*)u0p, out);  // k=19
}